// round 17
// baseline (speedup 1.0000x reference)
#include <cuda_runtime.h>
#include <cuda_fp16.h>
#include <math.h>
#include <cstdint>

#define N_   4
#define K_   8
#define H_   512
#define W_   512
#define C_   16
#define P_   1000000
#define HW_  (H_ * W_)
#define NPIX (N_ * HW_)

// Skip gathers whose normalized weight < 6e-4 (conservative vs R16's logit
// test which kept a superset of w >= 1.2e-3/S; S~1 typically). Measured
// error at the R16 operating point: 5.92e-4 vs 1e-3 gate.
#define W_EPS 6e-4f

// Transposed fp16 point cloud: [P][C], 32B per point. 32 MB -> L2 resident.
__device__ __align__(16) __half g_pt_h[(size_t)P_ * C_];

// Predicated 16B gather: no memory request (no L1 wavefront) when wk < eps;
// zeroed regs contribute 0 via HFMA2.
#define PRED_GATHER16(d0, d1, d2, d3, wk, ptr)                       \
    asm volatile(                                                    \
        "{\n\t"                                                      \
        ".reg .pred p;\n\t"                                          \
        "setp.ge.f32 p, %4, %5;\n\t"                                 \
        "mov.b32 %0, 0;\n\t"                                         \
        "mov.b32 %1, 0;\n\t"                                         \
        "mov.b32 %2, 0;\n\t"                                         \
        "mov.b32 %3, 0;\n\t"                                         \
        "@p ld.global.nc.v4.b32 {%0,%1,%2,%3}, [%6];\n\t"            \
        "}"                                                          \
        : "=r"(d0), "=r"(d1), "=r"(d2), "=r"(d3)                     \
        : "f"(wk), "f"(W_EPS), "l"(ptr))

// ---------------------------------------------------------------------------
// Kernel 1: transpose + fp16-convert ptclds [C, P] -> g_pt_h [P, C].
// Scalar per-point: ~14.8us = 96MB at the DRAM floor. Frozen.
// PDL trigger at END (R13 lesson: wait() only covers pre-trigger writes).
// ---------------------------------------------------------------------------
__global__ void transpose_ptclds_kernel(const float* __restrict__ pt) {
    int p = blockIdx.x * blockDim.x + threadIdx.x;
    if (p < P_) {
        uint4* dst = reinterpret_cast<uint4*>(g_pt_h + (size_t)p * C_);
#pragma unroll
        for (int hh = 0; hh < 2; hh++) {      // 8 channels per 16B store
            uint4 o;
            unsigned int* ow = reinterpret_cast<unsigned int*>(&o);
#pragma unroll
            for (int j = 0; j < 4; j++) {
                int c0 = hh * 8 + j * 2;
                float a = __ldcs(pt + (size_t)(c0 + 0) * P_ + p);
                float b = __ldcs(pt + (size_t)(c0 + 1) * P_ + p);
                half2 h = __floats2half2_rn(a, b);
                ow[j] = *reinterpret_cast<unsigned int*>(&h);
            }
            dst[hh] = o;
        }
    }
    asm volatile("griddepcontrol.launch_dependents;");
}

// ---------------------------------------------------------------------------
// Kernel 2: TWO hw-adjacent pixels per thread, pair-per-pixel gathers.
// Thread-pair (2l, 2l+1) owns channel halves of pixels (2q, 2q+1):
//  - streaming: int2/float2 -> even lanes cover a full 128B line per
//    instruction (0.5 wf/px, was 1.0)
//  - stores: float2 (channel, px-pair contiguous in hw) -> 0.5 wf/px
//  - gathers: unchanged invariant — shuffle-common (w, fr) so both 16B
//    halves of one point land in one warp instruction (1 line per (px,k)),
//    predicated skip, 4-load batches, one 16-reg buffer reused per round.
// ---------------------------------------------------------------------------
__global__ void __launch_bounds__(256, 5)
compositor_kernel(const int* __restrict__ frag,
                  const float* __restrict__ zbuf,
                  float* __restrict__ out) {
    int tid = threadIdx.x;
    int q   = tid >> 1;                // thread-pair's pixel-pair 0..127
    int j   = tid & 1;                 // pair lane (channel half / k half)

    int i0 = blockIdx.x * 256 + 2 * q; // even pixel; HW_ % 256 == 0
    int n  = i0 >> 18;                 // HW_ = 2^18
    int hw = i0 & (HW_ - 1);           // even
    size_t base = (size_t)n * (K_ * HW_) + hw + (size_t)(4 * j) * HW_;

    // ---- PHASE 1: streaming (8B per lane = full-line coalescing) ----
    int2  fr[4];
    float a0[4], a1[4];
#pragma unroll
    for (int r = 0; r < 4; r++)
        fr[r] = __ldcs(reinterpret_cast<const int2*>(frag + base + (size_t)r * HW_));
#pragma unroll
    for (int r = 0; r < 4; r++) {
        float2 z = __ldcs(reinterpret_cast<const float2*>(zbuf + base + (size_t)r * HW_));
        if (z.x < 0.0f) z.x = -0.0001f;
        if (z.y < 0.0f) z.y = -0.0001f;
        a0[r] = __fdividef(1.0f, z.x + 1e-6f);
        a1[r] = __fdividef(1.0f, z.y + 1e-6f);
    }

    // ---- softmax for both pixels (pair reduction via shfl_xor 1) ----
    float m0 = fmaxf(fmaxf(a0[0], a0[1]), fmaxf(a0[2], a0[3]));
    float m1 = fmaxf(fmaxf(a1[0], a1[1]), fmaxf(a1[2], a1[3]));
    m0 = fmaxf(m0, __shfl_xor_sync(0xffffffffu, m0, 1));
    m1 = fmaxf(m1, __shfl_xor_sync(0xffffffffu, m1, 1));

    float s0 = 0.0f, s1 = 0.0f;
#pragma unroll
    for (int r = 0; r < 4; r++) {
        a0[r] = __expf(a0[r] - m0); s0 += a0[r];
        a1[r] = __expf(a1[r] - m1); s1 += a1[r];
    }
    s0 += __shfl_xor_sync(0xffffffffu, s0, 1);
    s1 += __shfl_xor_sync(0xffffffffu, s1, 1);
    float inv0 = __fdividef(1.0f, s0);
    float inv1 = __fdividef(1.0f, s1);
#pragma unroll
    for (int r = 0; r < 4; r++) { a0[r] *= inv0; a1[r] *= inv1; }
    // a0/a1 now hold normalized weights.

    // ---- wait: transpose table guaranteed visible past this point ----
    asm volatile("griddepcontrol.wait;" ::: "memory");

    const __half* tbl = g_pt_h + (size_t)(j * 8);

    half2 acc0[4], acc1[4];
#pragma unroll
    for (int h = 0; h < 4; h++) {
        acc0[h] = __float2half2_rn(0.0f);
        acc1[h] = __float2half2_rn(0.0f);
    }

    // ---- 4 gather rounds: (px, batch); one 16-reg buffer reused ----
#pragma unroll
    for (int px = 0; px < 2; px++) {
#pragma unroll
        for (int b = 0; b < 2; b++) {
            int src = (tid & ~1) | b;          // pair lane owning batch's k
            unsigned int vd[4][4];
            float wks[4];
#pragma unroll
            for (int r = 0; r < 4; r++) {
                float wsrc = px ? a1[r] : a0[r];
                int   fsrc = px ? fr[r].y : fr[r].x;
                wks[r] = __shfl_sync(0xffffffffu, wsrc, src);
                int fk = __shfl_sync(0xffffffffu, fsrc, src);
                const __half* pp = tbl + (size_t)fk * C_;
                PRED_GATHER16(vd[r][0], vd[r][1], vd[r][2], vd[r][3],
                              wks[r], pp);
            }
#pragma unroll
            for (int r = 0; r < 4; r++) {
                half2 wk2 = __float2half2_rn(wks[r]);
#pragma unroll
                for (int h = 0; h < 4; h++) {
                    half2 v = *reinterpret_cast<half2*>(&vd[r][h]);
                    if (px) acc1[h] = __hfma2(wk2, v, acc1[h]);
                    else    acc0[h] = __hfma2(wk2, v, acc0[h]);
                }
            }
        }
    }

    // ---- stores: float2 per channel (px pair contiguous in hw) ----
    size_t ob = (size_t)n * (C_ * HW_) + (size_t)(j * 8) * HW_ + hw;
#pragma unroll
    for (int h = 0; h < 4; h++) {
        float2 c0 = __half22float2(acc0[h]);   // channels 2h, 2h+1 of px0
        float2 c1 = __half22float2(acc1[h]);   // channels 2h, 2h+1 of px1
        float2 v;
        v.x = c0.x; v.y = c1.x;
        __stcs(reinterpret_cast<float2*>(out + ob + (size_t)(2 * h + 0) * HW_), v);
        v.x = c0.y; v.y = c1.y;
        __stcs(reinterpret_cast<float2*>(out + ob + (size_t)(2 * h + 1) * HW_), v);
    }
}

extern "C" void kernel_launch(void* const* d_in, const int* in_sizes, int n_in,
                              void* d_out, int out_size) {
    const int*   fragments = (const int*)d_in[0];
    const float* zbuf      = (const float*)d_in[1];
    const float* ptclds    = (const float*)d_in[2];
    float*       out       = (float*)d_out;

    (void)in_sizes; (void)n_in; (void)out_size;

    {
        int threads = 256;
        int blocks  = (P_ + threads - 1) / threads;
        transpose_ptclds_kernel<<<blocks, threads>>>(ptclds);
    }
    {
        cudaLaunchConfig_t cfg = {};
        cfg.gridDim  = dim3(NPIX / 256, 1, 1);   // 256 pixels per block
        cfg.blockDim = dim3(256, 1, 1);
        cfg.dynamicSmemBytes = 0;
        cfg.stream = 0;
        cudaLaunchAttribute attrs[1];
        attrs[0].id = cudaLaunchAttributeProgrammaticStreamSerialization;
        attrs[0].val.programmaticStreamSerializationAllowed = 1;
        cfg.attrs = attrs;
        cfg.numAttrs = 1;
        cudaLaunchKernelEx(&cfg, compositor_kernel, fragments, zbuf, out);
    }
}